// round 15
// baseline (speedup 1.0000x reference)
#include <cuda_runtime.h>
#include <cuda_fp16.h>
#include <cstdint>

// ---------------------------------------------------------------------------
// Problem constants
// ---------------------------------------------------------------------------
constexpr int B_ = 4;
constexpr int N_ = 2048;
constexpr int D_ = 1024;
constexpr int M_ = B_ * N_;  // 8192 tokens

// ---------------------------------------------------------------------------
// Scratch (device globals — allocation is forbidden)
// ---------------------------------------------------------------------------
__device__ __half g_x16[M_ * D_];
__device__ __half g_Wt16[3][D_ * D_];       // W^T [e][d]
__device__ __half g_Q16[M_ * D_];
__device__ __half g_K16[M_ * D_];
__device__ __half g_V16[M_ * D_];
__device__ float g_S[(size_t)B_ * N_ * N_];
__device__ __half g_P16[(size_t)B_ * N_ * N_];

// ---------------------------------------------------------------------------
// Helpers
// ---------------------------------------------------------------------------
__device__ __forceinline__ uint32_t smem_u32(const void* p) {
  uint32_t a;
  asm("{ .reg .u64 t; cvta.to.shared.u64 t, %1; cvt.u32.u64 %0, t; }"
      : "=r"(a) : "l"(p));
  return a;
}

__device__ __forceinline__ void cp_async16(uint32_t smem, const void* g) {
  asm volatile("cp.async.cg.shared.global [%0], [%1], 16;" ::"r"(smem), "l"(g)
               : "memory");
}
#define CP_COMMIT() asm volatile("cp.async.commit_group;" ::: "memory")

__device__ __forceinline__ uint32_t swz128(uint32_t off) {  // 128B rows
  return off ^ ((off >> 3) & 0x70);
}
__device__ __forceinline__ uint32_t swz256(uint32_t off) {  // 256B rows
  return off ^ (((off >> 8) & 7) << 4);
}

__device__ __forceinline__ void ldmatrix_x4(uint32_t& r0, uint32_t& r1,
                                            uint32_t& r2, uint32_t& r3,
                                            uint32_t addr) {
  asm volatile(
      "ldmatrix.sync.aligned.m8n8.x4.shared.b16 {%0,%1,%2,%3}, [%4];"
      : "=r"(r0), "=r"(r1), "=r"(r2), "=r"(r3)
      : "r"(addr));
}

__device__ __forceinline__ void ldmatrix_x4_trans(uint32_t& r0, uint32_t& r1,
                                                  uint32_t& r2, uint32_t& r3,
                                                  uint32_t addr) {
  asm volatile(
      "ldmatrix.sync.aligned.m8n8.x4.trans.shared.b16 {%0,%1,%2,%3}, [%4];"
      : "=r"(r0), "=r"(r1), "=r"(r2), "=r"(r3)
      : "r"(addr));
}

__device__ __forceinline__ void mma_fp16(float* c, const uint32_t* a,
                                         uint32_t b0, uint32_t b1) {
  asm volatile(
      "mma.sync.aligned.m16n8k16.row.col.f32.f16.f16.f32 "
      "{%0,%1,%2,%3}, {%4,%5,%6,%7}, {%8,%9}, {%0,%1,%2,%3};"
      : "+f"(c[0]), "+f"(c[1]), "+f"(c[2]), "+f"(c[3])
      : "r"(a[0]), "r"(a[1]), "r"(a[2]), "r"(a[3]), "r"(b0), "r"(b1));
}

// ---------------------------------------------------------------------------
// Warp-tiled fp16 mma.sync GEMM, C[128x128], fp32 accumulation.
// 256 threads, 8 warps (4x2), warp tile 32x64. 2-stage BK=64 pipeline,
// single __syncthreads per step, occupancy 2 CTAs/SM.
// MODE 0: QKV proj  (A=x K-major,  B=W^T K-major rows; bz selects W/output)
// MODE 1: scores    (A=Q K-major,  B=K  K-major rows; causal tile skip)
// MODE 2: PV        (A=P K-major,  B=V natural [tok][e] + ldmatrix.trans;
//                    causal K bound; heavy tiles first)
// ---------------------------------------------------------------------------
constexpr int ASTG = 16384;        // 128 rows x 128B
constexpr int BSTG = 16384;        // mode01: 128 n-rows x 128B; mode2: 64 k-rows x 256B
constexpr int STG = ASTG + BSTG;   // 32 KB per stage
constexpr int SMEM_DYN = 1024 + 2 * STG;  // 66560
constexpr float SCALE = 0.03125f;  // 1/sqrt(1024)

template <int MODE>
__global__ __launch_bounds__(256, 2) void gemm_tc(float* out) {
  extern __shared__ char dsm[];

  const int bx = blockIdx.x, bz = blockIdx.z;
  const int by = (MODE == 2) ? (gridDim.y - 1 - blockIdx.y) : blockIdx.y;
  const int row0 = by * 128, col0 = bx * 128;

  const __half *ap, *bp;
  size_t lda;
  int nsteps;
  if constexpr (MODE == 0) {
    ap = g_x16;
    bp = g_Wt16[bz];
    lda = D_; nsteps = 16;
  } else if constexpr (MODE == 1) {
    if (bx > by) return;  // tile fully above the diagonal
    size_t o = (size_t)bz * N_ * D_;
    ap = g_Q16 + o;
    bp = g_K16 + o;
    lda = D_; nsteps = 16;
  } else {
    ap = g_P16 + (size_t)bz * N_ * N_;
    bp = g_V16 + (size_t)bz * N_ * D_;
    lda = N_; nsteps = 2 * (by + 1);  // causal: K = 128*(by+1), BK=64
  }

  const int tid = threadIdx.x;
  const int wid = tid >> 5, lid = tid & 31;
  const int wm = wid & 3, wn = wid >> 2;  // 4x2 warp grid; warp tile 32x64

  const uint32_t smA = (smem_u32(dsm) + 1023) & ~1023u;

  float acc[2][8][4];
#pragma unroll
  for (int i = 0; i < 2; ++i)
#pragma unroll
    for (int j = 0; j < 8; ++j)
#pragma unroll
      for (int k = 0; k < 4; ++k) acc[i][j][k] = 0.f;

  // ---- step loader (BK=64): 256 threads, A 4x cp16 + B 4x cp16 each ----
  auto load_step = [&](int c, int s) {
    const int k0 = c * 64;
    const uint32_t sa = smA + s * STG;
    const uint32_t sb = sa + ASTG;
    {  // A: 128 rows x 128B; thread t: row t>>1, half t&1
      const int r = tid >> 1, h = tid & 1;
      const uint32_t o0 = (uint32_t)(r * 128 + h * 64);
      const char* ag = (const char*)(ap + (size_t)(row0 + r) * lda + k0) + h * 64;
#pragma unroll
      for (int j = 0; j < 4; ++j)
        cp_async16(sa + swz128(o0 + j * 16), ag + j * 16);
    }
    if constexpr (MODE != 2) {
      // B: 128 n-rows x 128B K-major; thread t: row t>>1, half t&1
      const int r = tid >> 1, h = tid & 1;
      const uint32_t o0 = (uint32_t)(r * 128 + h * 64);
      const char* bg = (const char*)(bp + (size_t)(col0 + r) * lda + k0) + h * 64;
#pragma unroll
      for (int j = 0; j < 4; ++j)
        cp_async16(sb + swz128(o0 + j * 16), bg + j * 16);
    } else {
      // B: V natural layout, 64 k-rows x 256B (128 e cols)
      const int r = tid >> 2, seg = tid & 3;
      const uint32_t o0 = (uint32_t)(r * 256 + seg * 64);
      const char* bg = (const char*)(bp + (size_t)(k0 + r) * D_ + col0 + seg * 32);
#pragma unroll
      for (int j = 0; j < 4; ++j)
        cp_async16(sb + swz256(o0 + j * 16), bg + j * 16);
    }
    CP_COMMIT();
  };

  load_step(0, 0);

  for (int c = 0; c < nsteps; ++c) {
    asm volatile("cp.async.wait_group 0;" ::: "memory");
    __syncthreads();
    // Barrier also orders step c-1's compute (other-stage readers) before
    // the writes below — no trailing barrier needed.
    if (c + 1 < nsteps) load_step(c + 1, (c + 1) & 1);

    const uint32_t sa = smA + (c & 1) * STG;
    const uint32_t sb = sa + ASTG;

#pragma unroll
    for (int kk = 0; kk < 4; ++kk) {  // 4 x k16 per 64-wide step
      uint32_t af[2][4];
#pragma unroll
      for (int mt = 0; mt < 2; ++mt) {
        const int m0 = wm * 32 + mt * 16;
        const int row = m0 + ((lid >> 3) & 1) * 8 + (lid & 7);
        const int kb = kk * 32 + ((lid >> 4) & 1) * 16;
        ldmatrix_x4(af[mt][0], af[mt][1], af[mt][2], af[mt][3],
                    sa + row * 128 + (kb ^ ((row & 7) << 4)));
      }
      uint32_t bfr[4][4];
#pragma unroll
      for (int np = 0; np < 4; ++np) {
        if constexpr (MODE != 2) {
          const int n0 = wn * 64 + np * 16;
          const int row = n0 + ((lid >> 4) & 1) * 8 + (lid & 7);
          const int kb = kk * 32 + ((lid >> 3) & 1) * 16;
          ldmatrix_x4(bfr[np][0], bfr[np][1], bfr[np][2], bfr[np][3],
                      sb + row * 128 + (kb ^ ((row & 7) << 4)));
        } else {
          // transposed load from V[tok][e]: k-rows, e-cols
          const int krow = kk * 16 + ((lid >> 3) & 1) * 8 + (lid & 7);
          const int colb = (wn * 64 + np * 16 + ((lid >> 4) & 1) * 8) * 2;
          ldmatrix_x4_trans(bfr[np][0], bfr[np][1], bfr[np][2], bfr[np][3],
                            sb + krow * 256 + (colb ^ ((krow & 7) << 4)));
        }
      }
#pragma unroll
      for (int mt = 0; mt < 2; ++mt)
#pragma unroll
        for (int nt = 0; nt < 8; ++nt)
          mma_fp16(acc[mt][nt], af[mt], bfr[nt >> 1][(nt & 1) * 2],
                   bfr[nt >> 1][(nt & 1) * 2 + 1]);
    }
  }

  // ---- epilogue: fragment (c0,c1)=(m, n..n+1), (c2,c3)=(m+8, n..n+1) ----
#pragma unroll
  for (int mt = 0; mt < 2; ++mt) {
#pragma unroll
    for (int nt = 0; nt < 8; ++nt) {
      const int m = row0 + wm * 32 + mt * 16 + (lid >> 2);
      const int n = col0 + wn * 64 + nt * 8 + 2 * (lid & 3);
      const float* cf = acc[mt][nt];
      if constexpr (MODE == 0) {
        __half* C = (bz == 0) ? g_Q16 : (bz == 1) ? g_K16 : g_V16;
#pragma unroll
        for (int hh = 0; hh < 2; ++hh) {
          const size_t o = (size_t)(m + hh * 8) * D_ + n;
          *(__half2*)(C + o) = __floats2half2_rn(cf[hh * 2], cf[hh * 2 + 1]);
        }
      } else if constexpr (MODE == 1) {
#pragma unroll
        for (int hh = 0; hh < 2; ++hh) {
          float* sp = g_S + ((size_t)bz * N_ + m + hh * 8) * N_ + n;
          sp[0] = cf[hh * 2] * SCALE;
          sp[1] = cf[hh * 2 + 1] * SCALE;
        }
      } else {
#pragma unroll
        for (int hh = 0; hh < 2; ++hh) {
          float* op = out + ((size_t)bz * N_ + m + hh * 8) * D_ + n;
          op[0] = cf[hh * 2];
          op[1] = cf[hh * 2 + 1];
        }
      }
    }
  }
}

// ---------------------------------------------------------------------------
// Fused conversion: z = 0..3 -> x quarters (coalesced fp32->fp16),
//                   z = 4..6 -> transpose-convert W[d][e] -> Wt16[e][d]
// ---------------------------------------------------------------------------
__global__ __launch_bounds__(256) void conv_all_kernel(
    const float* __restrict__ x, const float* __restrict__ Wq,
    const float* __restrict__ Wk, const float* __restrict__ Wv) {
  const int z = blockIdx.z;
  if (z < 4) {
    // x quarter z: 2M elements, 1024 blocks x 256 threads x 8 elems (2 float4)
    size_t base = (size_t)z * (M_ * D_ / 4);
    size_t i = base + ((size_t)blockIdx.x * 256 + threadIdx.x) * 8;
    float4 v0 = *(const float4*)(x + i);
    float4 v1 = *(const float4*)(x + i + 4);
    __half2* o = (__half2*)(g_x16 + i);
    o[0] = __floats2half2_rn(v0.x, v0.y);
    o[1] = __floats2half2_rn(v0.z, v0.w);
    o[2] = __floats2half2_rn(v1.x, v1.y);
    o[3] = __floats2half2_rn(v1.z, v1.w);
  } else {
    const int w = z - 4;
    const float* W = (w == 0) ? Wq : (w == 1) ? Wk : Wv;
    __half* T = g_Wt16[w];
    __shared__ float t[32][33];
    // blockIdx.x in [0, 1024): 32x32 tile grid over [D_, D_]
    int e0 = (blockIdx.x & 31) * 32, d0 = (blockIdx.x >> 5) * 32;
    int tx = threadIdx.x & 31, ty = threadIdx.x >> 5;  // 32 x 8
#pragma unroll
    for (int i = 0; i < 4; ++i)
      t[ty + i * 8][tx] = W[(size_t)(d0 + ty + i * 8) * D_ + e0 + tx];
    __syncthreads();
#pragma unroll
    for (int i = 0; i < 4; ++i)
      T[(size_t)(e0 + ty + i * 8) * D_ + d0 + tx] =
          __float2half_rn(t[tx][ty + i * 8]);
  }
}

// ---------------------------------------------------------------------------
// Causal softmax, register-resident + balanced: each block handles the row
// pair (q, N-1-q); each thread holds its <=8 strided elements in registers
// (no smem staging). Shuffle + 8-slot smem reductions. fp16 stores are
// zero-padded to the 128-aligned causal tile bound (what the PV GEMM reads).
// ---------------------------------------------------------------------------
__global__ __launch_bounds__(256) void softmax_kernel() {
  const int b = blockIdx.y;
  const int tid = threadIdx.x;

  __shared__ float redm[8], reds[8];

#pragma unroll
  for (int half = 0; half < 2; ++half) {
    const int q = half ? (N_ - 1 - blockIdx.x) : blockIdx.x;
    const float* row = g_S + ((size_t)b * N_ + q) * N_;
    __half* ph = g_P16 + ((size_t)b * N_ + q) * N_;
    const int L = q + 1;
    const int nIt = (L + 255) >> 8;        // per-thread element count
    const int wlim = ((q >> 7) + 1) << 7;  // PV reads cols [0, wlim)

    // pass 1: gmem -> registers, local max
    float a[8];
    float m = -1e30f;
#pragma unroll
    for (int i = 0; i < 8; ++i) {
      if (i < nIt) {
        const int k = i * 256 + tid;
        a[i] = (k < L) ? row[k] : -1e30f;
        m = fmaxf(m, a[i]);
      }
    }
#pragma unroll
    for (int o = 16; o; o >>= 1) m = fmaxf(m, __shfl_xor_sync(~0u, m, o));
    if ((tid & 31) == 0) redm[tid >> 5] = m;
    __syncthreads();
    float m0 = redm[0];
#pragma unroll
    for (int w = 1; w < 8; ++w) m0 = fmaxf(m0, redm[w]);

    // pass 2: exp in registers, local sum
    float sum = 0.f;
    const float c = 1.44269504f;
#pragma unroll
    for (int i = 0; i < 8; ++i) {
      if (i < nIt) {
        a[i] = exp2f((a[i] - m0) * c);
        sum += a[i];
      }
    }
#pragma unroll
    for (int o = 16; o; o >>= 1) sum += __shfl_xor_sync(~0u, sum, o);
    if ((tid & 31) == 0) reds[tid >> 5] = sum;
    __syncthreads();
    float s0 = 0.f;
#pragma unroll
    for (int w = 0; w < 8; ++w) s0 += reds[w];
    const float inv = 1.f / s0;

    // pass 3: normalize + fp16 store (zeros to the tile bound)
#pragma unroll
    for (int i = 0; i < 8; ++i) {
      const int k = i * 256 + tid;
      if (k < wlim)
        ph[k] = __float2half_rn(k < L ? a[i] * inv : 0.f);
    }
    __syncthreads();  // redm/reds reuse between the two rows
  }
}

// ---------------------------------------------------------------------------
extern "C" void kernel_launch(void* const* d_in, const int* in_sizes, int n_in,
                              void* d_out, int out_size) {
  const float* x  = (const float*)d_in[0];
  const float* Wq = (const float*)d_in[1];
  const float* Wk = (const float*)d_in[2];
  const float* Wv = (const float*)d_in[3];
  float* out = (float*)d_out;

  cudaFuncSetAttribute(gemm_tc<0>, cudaFuncAttributeMaxDynamicSharedMemorySize,
                       SMEM_DYN);
  cudaFuncSetAttribute(gemm_tc<1>, cudaFuncAttributeMaxDynamicSharedMemorySize,
                       SMEM_DYN);
  cudaFuncSetAttribute(gemm_tc<2>, cudaFuncAttributeMaxDynamicSharedMemorySize,
                       SMEM_DYN);

  // 1) fused conversion: x -> fp16, W -> fp16 transposed
  conv_all_kernel<<<dim3(1024, 1, 7), 256>>>(x, Wq, Wk, Wv);
  // 2) QKV projections: C[8192,1024], 128x128 tiles
  gemm_tc<0><<<dim3(D_ / 128, M_ / 128, 3), 256, SMEM_DYN>>>(nullptr);
  // 3) scores S = scale * Q K^T (tiles above the diagonal skipped)
  gemm_tc<1><<<dim3(N_ / 128, N_ / 128, B_), 256, SMEM_DYN>>>(nullptr);
  // 4) softmax -> P fp16 (balanced row pairs, register-resident)
  softmax_kernel<<<dim3(N_ / 2, B_), 256>>>();
  // 5) O = P V (causally bounded K loop, heavy tiles first, V loaded direct)
  gemm_tc<2><<<dim3(D_ / 128, N_ / 128, B_), 256, SMEM_DYN>>>(out);
}

// round 16
// speedup vs baseline: 1.0169x; 1.0169x over previous
#include <cuda_runtime.h>
#include <cuda_fp16.h>
#include <cstdint>

// ---------------------------------------------------------------------------
// Problem constants
// ---------------------------------------------------------------------------
constexpr int B_ = 4;
constexpr int N_ = 2048;
constexpr int D_ = 1024;
constexpr int M_ = B_ * N_;  // 8192 tokens

// ---------------------------------------------------------------------------
// Scratch (device globals — allocation is forbidden)
// ---------------------------------------------------------------------------
__device__ __half g_x16[M_ * D_];
__device__ __half g_Wt16[3][D_ * D_];       // W^T [e][d]
__device__ __half g_Q16[M_ * D_];
__device__ __half g_K16[M_ * D_];
__device__ __half g_V16[M_ * D_];
__device__ float g_S[(size_t)B_ * N_ * N_];
__device__ __half g_P16[(size_t)B_ * N_ * N_];

// ---------------------------------------------------------------------------
// Helpers
// ---------------------------------------------------------------------------
__device__ __forceinline__ uint32_t smem_u32(const void* p) {
  uint32_t a;
  asm("{ .reg .u64 t; cvta.to.shared.u64 t, %1; cvt.u32.u64 %0, t; }"
      : "=r"(a) : "l"(p));
  return a;
}

__device__ __forceinline__ void cp_async16(uint32_t smem, const void* g) {
  asm volatile("cp.async.cg.shared.global [%0], [%1], 16;" ::"r"(smem), "l"(g)
               : "memory");
}
#define CP_COMMIT() asm volatile("cp.async.commit_group;" ::: "memory")

__device__ __forceinline__ uint32_t swz128(uint32_t off) {  // 128B rows
  return off ^ ((off >> 3) & 0x70);
}
__device__ __forceinline__ uint32_t swz256(uint32_t off) {  // 256B rows
  return off ^ (((off >> 8) & 7) << 4);
}

__device__ __forceinline__ void ldmatrix_x4(uint32_t& r0, uint32_t& r1,
                                            uint32_t& r2, uint32_t& r3,
                                            uint32_t addr) {
  asm volatile(
      "ldmatrix.sync.aligned.m8n8.x4.shared.b16 {%0,%1,%2,%3}, [%4];"
      : "=r"(r0), "=r"(r1), "=r"(r2), "=r"(r3)
      : "r"(addr));
}

__device__ __forceinline__ void ldmatrix_x4_trans(uint32_t& r0, uint32_t& r1,
                                                  uint32_t& r2, uint32_t& r3,
                                                  uint32_t addr) {
  asm volatile(
      "ldmatrix.sync.aligned.m8n8.x4.trans.shared.b16 {%0,%1,%2,%3}, [%4];"
      : "=r"(r0), "=r"(r1), "=r"(r2), "=r"(r3)
      : "r"(addr));
}

__device__ __forceinline__ void mma_fp16(float* c, const uint32_t* a,
                                         uint32_t b0, uint32_t b1) {
  asm volatile(
      "mma.sync.aligned.m16n8k16.row.col.f32.f16.f16.f32 "
      "{%0,%1,%2,%3}, {%4,%5,%6,%7}, {%8,%9}, {%0,%1,%2,%3};"
      : "+f"(c[0]), "+f"(c[1]), "+f"(c[2]), "+f"(c[3])
      : "r"(a[0]), "r"(a[1]), "r"(a[2]), "r"(a[3]), "r"(b0), "r"(b1));
}

// ---------------------------------------------------------------------------
// Warp-tiled fp16 mma.sync GEMM, C[128x128], fp32 accumulation.
// 256 threads, 8 warps (4x2), warp tile 32x64. 2-stage BK=64 pipeline,
// single __syncthreads per step, occupancy 2 CTAs/SM.
// MODE 0: QKV proj  (A=x K-major,  B=W^T K-major rows; bz selects W/output)
// MODE 1: scores    (A=Q K-major,  B=K  K-major rows; causal tile skip)
// MODE 2: PV        (A=P K-major,  B=V natural [tok][e] + ldmatrix.trans;
//                    causal K bound; heavy tiles first)
// ---------------------------------------------------------------------------
constexpr int ASTG = 16384;        // 128 rows x 128B
constexpr int BSTG = 16384;        // mode01: 128 n-rows x 128B; mode2: 64 k-rows x 256B
constexpr int STG = ASTG + BSTG;   // 32 KB per stage
constexpr int SMEM_DYN = 1024 + 2 * STG;  // 66560
constexpr float SCALE = 0.03125f;  // 1/sqrt(1024)

template <int MODE>
__global__ __launch_bounds__(256, 2) void gemm_tc(float* out) {
  extern __shared__ char dsm[];

  const int bx = blockIdx.x, bz = blockIdx.z;
  const int by = (MODE == 2) ? (gridDim.y - 1 - blockIdx.y) : blockIdx.y;
  const int row0 = by * 128, col0 = bx * 128;

  const __half *ap, *bp;
  size_t lda;
  int nsteps;
  if constexpr (MODE == 0) {
    ap = g_x16;
    bp = g_Wt16[bz];
    lda = D_; nsteps = 16;
  } else if constexpr (MODE == 1) {
    if (bx > by) return;  // tile fully above the diagonal
    size_t o = (size_t)bz * N_ * D_;
    ap = g_Q16 + o;
    bp = g_K16 + o;
    lda = D_; nsteps = 16;
  } else {
    ap = g_P16 + (size_t)bz * N_ * N_;
    bp = g_V16 + (size_t)bz * N_ * D_;
    lda = N_; nsteps = 2 * (by + 1);  // causal: K = 128*(by+1), BK=64
  }

  const int tid = threadIdx.x;
  const int wid = tid >> 5, lid = tid & 31;
  const int wm = wid & 3, wn = wid >> 2;  // 4x2 warp grid; warp tile 32x64

  const uint32_t smA = (smem_u32(dsm) + 1023) & ~1023u;

  float acc[2][8][4];
#pragma unroll
  for (int i = 0; i < 2; ++i)
#pragma unroll
    for (int j = 0; j < 8; ++j)
#pragma unroll
      for (int k = 0; k < 4; ++k) acc[i][j][k] = 0.f;

  // ---- step loader (BK=64): 256 threads, A 4x cp16 + B 4x cp16 each ----
  auto load_step = [&](int c, int s) {
    const int k0 = c * 64;
    const uint32_t sa = smA + s * STG;
    const uint32_t sb = sa + ASTG;
    {  // A: 128 rows x 128B; thread t: row t>>1, half t&1
      const int r = tid >> 1, h = tid & 1;
      const uint32_t o0 = (uint32_t)(r * 128 + h * 64);
      const char* ag = (const char*)(ap + (size_t)(row0 + r) * lda + k0) + h * 64;
#pragma unroll
      for (int j = 0; j < 4; ++j)
        cp_async16(sa + swz128(o0 + j * 16), ag + j * 16);
    }
    if constexpr (MODE != 2) {
      // B: 128 n-rows x 128B K-major; thread t: row t>>1, half t&1
      const int r = tid >> 1, h = tid & 1;
      const uint32_t o0 = (uint32_t)(r * 128 + h * 64);
      const char* bg = (const char*)(bp + (size_t)(col0 + r) * lda + k0) + h * 64;
#pragma unroll
      for (int j = 0; j < 4; ++j)
        cp_async16(sb + swz128(o0 + j * 16), bg + j * 16);
    } else {
      // B: V natural layout, 64 k-rows x 256B (128 e cols)
      const int r = tid >> 2, seg = tid & 3;
      const uint32_t o0 = (uint32_t)(r * 256 + seg * 64);
      const char* bg = (const char*)(bp + (size_t)(k0 + r) * D_ + col0 + seg * 32);
#pragma unroll
      for (int j = 0; j < 4; ++j)
        cp_async16(sb + swz256(o0 + j * 16), bg + j * 16);
    }
    CP_COMMIT();
  };

  load_step(0, 0);

  for (int c = 0; c < nsteps; ++c) {
    asm volatile("cp.async.wait_group 0;" ::: "memory");
    __syncthreads();
    // Barrier also orders step c-1's compute (other-stage readers) before
    // the writes below — no trailing barrier needed.
    if (c + 1 < nsteps) load_step(c + 1, (c + 1) & 1);

    const uint32_t sa = smA + (c & 1) * STG;
    const uint32_t sb = sa + ASTG;

#pragma unroll
    for (int kk = 0; kk < 4; ++kk) {  // 4 x k16 per 64-wide step
      uint32_t af[2][4];
#pragma unroll
      for (int mt = 0; mt < 2; ++mt) {
        const int m0 = wm * 32 + mt * 16;
        const int row = m0 + ((lid >> 3) & 1) * 8 + (lid & 7);
        const int kb = kk * 32 + ((lid >> 4) & 1) * 16;
        ldmatrix_x4(af[mt][0], af[mt][1], af[mt][2], af[mt][3],
                    sa + row * 128 + (kb ^ ((row & 7) << 4)));
      }
      uint32_t bfr[4][4];
#pragma unroll
      for (int np = 0; np < 4; ++np) {
        if constexpr (MODE != 2) {
          const int n0 = wn * 64 + np * 16;
          const int row = n0 + ((lid >> 4) & 1) * 8 + (lid & 7);
          const int kb = kk * 32 + ((lid >> 3) & 1) * 16;
          ldmatrix_x4(bfr[np][0], bfr[np][1], bfr[np][2], bfr[np][3],
                      sb + row * 128 + (kb ^ ((row & 7) << 4)));
        } else {
          // transposed load from V[tok][e]: k-rows, e-cols
          const int krow = kk * 16 + ((lid >> 3) & 1) * 8 + (lid & 7);
          const int colb = (wn * 64 + np * 16 + ((lid >> 4) & 1) * 8) * 2;
          ldmatrix_x4_trans(bfr[np][0], bfr[np][1], bfr[np][2], bfr[np][3],
                            sb + krow * 256 + (colb ^ ((krow & 7) << 4)));
        }
      }
#pragma unroll
      for (int mt = 0; mt < 2; ++mt)
#pragma unroll
        for (int nt = 0; nt < 8; ++nt)
          mma_fp16(acc[mt][nt], af[mt], bfr[nt >> 1][(nt & 1) * 2],
                   bfr[nt >> 1][(nt & 1) * 2 + 1]);
    }
  }

  // ---- epilogue: fragment (c0,c1)=(m, n..n+1), (c2,c3)=(m+8, n..n+1) ----
#pragma unroll
  for (int mt = 0; mt < 2; ++mt) {
#pragma unroll
    for (int nt = 0; nt < 8; ++nt) {
      const int m = row0 + wm * 32 + mt * 16 + (lid >> 2);
      const int n = col0 + wn * 64 + nt * 8 + 2 * (lid & 3);
      const float* cf = acc[mt][nt];
      if constexpr (MODE == 0) {
        __half* C = (bz == 0) ? g_Q16 : (bz == 1) ? g_K16 : g_V16;
#pragma unroll
        for (int hh = 0; hh < 2; ++hh) {
          const size_t o = (size_t)(m + hh * 8) * D_ + n;
          *(__half2*)(C + o) = __floats2half2_rn(cf[hh * 2], cf[hh * 2 + 1]);
        }
      } else if constexpr (MODE == 1) {
#pragma unroll
        for (int hh = 0; hh < 2; ++hh) {
          float* sp = g_S + ((size_t)bz * N_ + m + hh * 8) * N_ + n;
          sp[0] = cf[hh * 2] * SCALE;
          sp[1] = cf[hh * 2 + 1] * SCALE;
        }
      } else {
#pragma unroll
        for (int hh = 0; hh < 2; ++hh) {
          float* op = out + ((size_t)bz * N_ + m + hh * 8) * D_ + n;
          op[0] = cf[hh * 2];
          op[1] = cf[hh * 2 + 1];
        }
      }
    }
  }
}

// ---------------------------------------------------------------------------
// Fused conversion: z = 0..3 -> x quarters (coalesced fp32->fp16),
//                   z = 4..6 -> transpose-convert W[d][e] -> Wt16[e][d]
// ---------------------------------------------------------------------------
__global__ __launch_bounds__(256) void conv_all_kernel(
    const float* __restrict__ x, const float* __restrict__ Wq,
    const float* __restrict__ Wk, const float* __restrict__ Wv) {
  const int z = blockIdx.z;
  if (z < 4) {
    // x quarter z: 2M elements, 1024 blocks x 256 threads x 8 elems (2 float4)
    size_t base = (size_t)z * (M_ * D_ / 4);
    size_t i = base + ((size_t)blockIdx.x * 256 + threadIdx.x) * 8;
    float4 v0 = *(const float4*)(x + i);
    float4 v1 = *(const float4*)(x + i + 4);
    __half2* o = (__half2*)(g_x16 + i);
    o[0] = __floats2half2_rn(v0.x, v0.y);
    o[1] = __floats2half2_rn(v0.z, v0.w);
    o[2] = __floats2half2_rn(v1.x, v1.y);
    o[3] = __floats2half2_rn(v1.z, v1.w);
  } else {
    const int w = z - 4;
    const float* W = (w == 0) ? Wq : (w == 1) ? Wk : Wv;
    __half* T = g_Wt16[w];
    __shared__ float t[32][33];
    // blockIdx.x in [0, 1024): 32x32 tile grid over [D_, D_]
    int e0 = (blockIdx.x & 31) * 32, d0 = (blockIdx.x >> 5) * 32;
    int tx = threadIdx.x & 31, ty = threadIdx.x >> 5;  // 32 x 8
#pragma unroll
    for (int i = 0; i < 4; ++i)
      t[ty + i * 8][tx] = W[(size_t)(d0 + ty + i * 8) * D_ + e0 + tx];
    __syncthreads();
#pragma unroll
    for (int i = 0; i < 4; ++i)
      T[(size_t)(e0 + ty + i * 8) * D_ + d0 + tx] =
          __float2half_rn(t[tx][ty + i * 8]);
  }
}

// ---------------------------------------------------------------------------
// Causal softmax: register-resident, vectorized, balanced.
// Block handles the row pair (q, N-1-q). Thread tid owns the contiguous
// slice [tid*8, tid*8+8): 2x float4 loads, exp in registers, 4x __half2
// stores zero-padded to the 128-aligned causal tile bound.
// ---------------------------------------------------------------------------
__global__ __launch_bounds__(256) void softmax_kernel() {
  const int b = blockIdx.y;
  const int tid = threadIdx.x;

  __shared__ float redm[8], reds[8];

#pragma unroll
  for (int half = 0; half < 2; ++half) {
    const int q = half ? (N_ - 1 - blockIdx.x) : blockIdx.x;
    const float* row = g_S + ((size_t)b * N_ + q) * N_;
    __half* ph = g_P16 + ((size_t)b * N_ + q) * N_;
    const int L = q + 1;
    const int wlim = ((q >> 7) + 1) << 7;  // PV reads cols [0, wlim)
    const int k0 = tid * 8;                // this thread's slice start

    // pass 1: gmem -> registers (2x float4), masked, local max
    float a[8];
#pragma unroll
    for (int v = 0; v < 2; ++v) {
      const int k = k0 + v * 4;
      if (k < L) {
        float4 f = *(const float4*)(row + k);
        a[v * 4 + 0] = f.x;
        a[v * 4 + 1] = (k + 1 < L) ? f.y : -1e30f;
        a[v * 4 + 2] = (k + 2 < L) ? f.z : -1e30f;
        a[v * 4 + 3] = (k + 3 < L) ? f.w : -1e30f;
      } else {
        a[v * 4 + 0] = a[v * 4 + 1] = a[v * 4 + 2] = a[v * 4 + 3] = -1e30f;
      }
    }
    float m = a[0];
#pragma unroll
    for (int i = 1; i < 8; ++i) m = fmaxf(m, a[i]);
#pragma unroll
    for (int o = 16; o; o >>= 1) m = fmaxf(m, __shfl_xor_sync(~0u, m, o));
    if ((tid & 31) == 0) redm[tid >> 5] = m;
    __syncthreads();
    float m0 = redm[0];
#pragma unroll
    for (int w = 1; w < 8; ++w) m0 = fmaxf(m0, redm[w]);

    // pass 2: exp in registers, local sum (masked lanes give exp(-inf)=0)
    float sum = 0.f;
    const float c = 1.44269504f;
#pragma unroll
    for (int i = 0; i < 8; ++i) {
      a[i] = exp2f((a[i] - m0) * c);
      sum += a[i];
    }
#pragma unroll
    for (int o = 16; o; o >>= 1) sum += __shfl_xor_sync(~0u, sum, o);
    if ((tid & 31) == 0) reds[tid >> 5] = sum;
    __syncthreads();
    float s0 = 0.f;
#pragma unroll
    for (int w = 0; w < 8; ++w) s0 += reds[w];
    const float inv = 1.f / s0;

    // pass 3: normalize + 4x __half2 store (zeros land beyond L; bound wlim)
    if (k0 < wlim) {
#pragma unroll
      for (int p = 0; p < 4; ++p) {
        const int k = k0 + p * 2;
        float p0 = (k < L) ? a[p * 2] * inv : 0.f;
        float p1 = (k + 1 < L) ? a[p * 2 + 1] * inv : 0.f;
        *(__half2*)(ph + k) = __floats2half2_rn(p0, p1);
      }
    }
    __syncthreads();  // redm/reds reuse between the two rows
  }
}

// ---------------------------------------------------------------------------
extern "C" void kernel_launch(void* const* d_in, const int* in_sizes, int n_in,
                              void* d_out, int out_size) {
  const float* x  = (const float*)d_in[0];
  const float* Wq = (const float*)d_in[1];
  const float* Wk = (const float*)d_in[2];
  const float* Wv = (const float*)d_in[3];
  float* out = (float*)d_out;

  cudaFuncSetAttribute(gemm_tc<0>, cudaFuncAttributeMaxDynamicSharedMemorySize,
                       SMEM_DYN);
  cudaFuncSetAttribute(gemm_tc<1>, cudaFuncAttributeMaxDynamicSharedMemorySize,
                       SMEM_DYN);
  cudaFuncSetAttribute(gemm_tc<2>, cudaFuncAttributeMaxDynamicSharedMemorySize,
                       SMEM_DYN);

  // 1) fused conversion: x -> fp16, W -> fp16 transposed
  conv_all_kernel<<<dim3(1024, 1, 7), 256>>>(x, Wq, Wk, Wv);
  // 2) QKV projections: C[8192,1024], 128x128 tiles
  gemm_tc<0><<<dim3(D_ / 128, M_ / 128, 3), 256, SMEM_DYN>>>(nullptr);
  // 3) scores S = scale * Q K^T (tiles above the diagonal skipped)
  gemm_tc<1><<<dim3(N_ / 128, N_ / 128, B_), 256, SMEM_DYN>>>(nullptr);
  // 4) softmax -> P fp16 (balanced pairs, register-resident, vectorized)
  softmax_kernel<<<dim3(N_ / 2, B_), 256>>>();
  // 5) O = P V (causally bounded K loop, heavy tiles first, V loaded direct)
  gemm_tc<2><<<dim3(D_ / 128, N_ / 128, B_), 256, SMEM_DYN>>>(out);
}

// round 17
// speedup vs baseline: 1.0288x; 1.0116x over previous
#include <cuda_runtime.h>
#include <cuda_fp16.h>
#include <cstdint>

// ---------------------------------------------------------------------------
// Problem constants
// ---------------------------------------------------------------------------
constexpr int B_ = 4;
constexpr int N_ = 2048;
constexpr int D_ = 1024;
constexpr int M_ = B_ * N_;  // 8192 tokens

// ---------------------------------------------------------------------------
// Scratch (device globals — allocation is forbidden)
// ---------------------------------------------------------------------------
__device__ __half g_x16[M_ * D_];
__device__ __half g_Wt16[3][D_ * D_];       // W^T [e][d]
__device__ __half g_Q16[M_ * D_];
__device__ __half g_K16[M_ * D_];
__device__ __half g_V16[M_ * D_];
__device__ __half g_S16[(size_t)B_ * N_ * N_];  // scores, fp16
__device__ __half g_P16[(size_t)B_ * N_ * N_];

// ---------------------------------------------------------------------------
// Helpers
// ---------------------------------------------------------------------------
__device__ __forceinline__ uint32_t smem_u32(const void* p) {
  uint32_t a;
  asm("{ .reg .u64 t; cvta.to.shared.u64 t, %1; cvt.u32.u64 %0, t; }"
      : "=r"(a) : "l"(p));
  return a;
}

__device__ __forceinline__ void cp_async16(uint32_t smem, const void* g) {
  asm volatile("cp.async.cg.shared.global [%0], [%1], 16;" ::"r"(smem), "l"(g)
               : "memory");
}
#define CP_COMMIT() asm volatile("cp.async.commit_group;" ::: "memory")

__device__ __forceinline__ uint32_t swz128(uint32_t off) {  // 128B rows
  return off ^ ((off >> 3) & 0x70);
}
__device__ __forceinline__ uint32_t swz256(uint32_t off) {  // 256B rows
  return off ^ (((off >> 8) & 7) << 4);
}

__device__ __forceinline__ void ldmatrix_x4(uint32_t& r0, uint32_t& r1,
                                            uint32_t& r2, uint32_t& r3,
                                            uint32_t addr) {
  asm volatile(
      "ldmatrix.sync.aligned.m8n8.x4.shared.b16 {%0,%1,%2,%3}, [%4];"
      : "=r"(r0), "=r"(r1), "=r"(r2), "=r"(r3)
      : "r"(addr));
}

__device__ __forceinline__ void ldmatrix_x4_trans(uint32_t& r0, uint32_t& r1,
                                                  uint32_t& r2, uint32_t& r3,
                                                  uint32_t addr) {
  asm volatile(
      "ldmatrix.sync.aligned.m8n8.x4.trans.shared.b16 {%0,%1,%2,%3}, [%4];"
      : "=r"(r0), "=r"(r1), "=r"(r2), "=r"(r3)
      : "r"(addr));
}

__device__ __forceinline__ void mma_fp16(float* c, const uint32_t* a,
                                         uint32_t b0, uint32_t b1) {
  asm volatile(
      "mma.sync.aligned.m16n8k16.row.col.f32.f16.f16.f32 "
      "{%0,%1,%2,%3}, {%4,%5,%6,%7}, {%8,%9}, {%0,%1,%2,%3};"
      : "+f"(c[0]), "+f"(c[1]), "+f"(c[2]), "+f"(c[3])
      : "r"(a[0]), "r"(a[1]), "r"(a[2]), "r"(a[3]), "r"(b0), "r"(b1));
}

// ---------------------------------------------------------------------------
// Warp-tiled fp16 mma.sync GEMM, C[128x128], fp32 accumulation.
// 256 threads, 8 warps (4x2), warp tile 32x64. 2-stage BK=64 pipeline,
// single __syncthreads per step, occupancy 2 CTAs/SM.
// MODE 0: QKV proj  (A=x K-major,  B=W^T K-major rows; bz selects W/output)
// MODE 1: scores    (A=Q K-major,  B=K  K-major rows; causal tile skip;
//                    epilogue stores fp16 S)
// MODE 2: PV        (A=P K-major,  B=V natural [tok][e] + ldmatrix.trans;
//                    causal K bound; heavy tiles first)
// ---------------------------------------------------------------------------
constexpr int ASTG = 16384;        // 128 rows x 128B
constexpr int BSTG = 16384;        // mode01: 128 n-rows x 128B; mode2: 64 k-rows x 256B
constexpr int STG = ASTG + BSTG;   // 32 KB per stage
constexpr int SMEM_DYN = 1024 + 2 * STG;  // 66560
constexpr float SCALE = 0.03125f;  // 1/sqrt(1024)

template <int MODE>
__global__ __launch_bounds__(256, 2) void gemm_tc(float* out) {
  extern __shared__ char dsm[];

  const int bx = blockIdx.x, bz = blockIdx.z;
  const int by = (MODE == 2) ? (gridDim.y - 1 - blockIdx.y) : blockIdx.y;
  const int row0 = by * 128, col0 = bx * 128;

  const __half *ap, *bp;
  size_t lda;
  int nsteps;
  if constexpr (MODE == 0) {
    ap = g_x16;
    bp = g_Wt16[bz];
    lda = D_; nsteps = 16;
  } else if constexpr (MODE == 1) {
    if (bx > by) return;  // tile fully above the diagonal
    size_t o = (size_t)bz * N_ * D_;
    ap = g_Q16 + o;
    bp = g_K16 + o;
    lda = D_; nsteps = 16;
  } else {
    ap = g_P16 + (size_t)bz * N_ * N_;
    bp = g_V16 + (size_t)bz * N_ * D_;
    lda = N_; nsteps = 2 * (by + 1);  // causal: K = 128*(by+1), BK=64
  }

  const int tid = threadIdx.x;
  const int wid = tid >> 5, lid = tid & 31;
  const int wm = wid & 3, wn = wid >> 2;  // 4x2 warp grid; warp tile 32x64

  const uint32_t smA = (smem_u32(dsm) + 1023) & ~1023u;

  float acc[2][8][4];
#pragma unroll
  for (int i = 0; i < 2; ++i)
#pragma unroll
    for (int j = 0; j < 8; ++j)
#pragma unroll
      for (int k = 0; k < 4; ++k) acc[i][j][k] = 0.f;

  // ---- step loader (BK=64): 256 threads, A 4x cp16 + B 4x cp16 each ----
  auto load_step = [&](int c, int s) {
    const int k0 = c * 64;
    const uint32_t sa = smA + s * STG;
    const uint32_t sb = sa + ASTG;
    {  // A: 128 rows x 128B; thread t: row t>>1, half t&1
      const int r = tid >> 1, h = tid & 1;
      const uint32_t o0 = (uint32_t)(r * 128 + h * 64);
      const char* ag = (const char*)(ap + (size_t)(row0 + r) * lda + k0) + h * 64;
#pragma unroll
      for (int j = 0; j < 4; ++j)
        cp_async16(sa + swz128(o0 + j * 16), ag + j * 16);
    }
    if constexpr (MODE != 2) {
      // B: 128 n-rows x 128B K-major; thread t: row t>>1, half t&1
      const int r = tid >> 1, h = tid & 1;
      const uint32_t o0 = (uint32_t)(r * 128 + h * 64);
      const char* bg = (const char*)(bp + (size_t)(col0 + r) * lda + k0) + h * 64;
#pragma unroll
      for (int j = 0; j < 4; ++j)
        cp_async16(sb + swz128(o0 + j * 16), bg + j * 16);
    } else {
      // B: V natural layout, 64 k-rows x 256B (128 e cols)
      const int r = tid >> 2, seg = tid & 3;
      const uint32_t o0 = (uint32_t)(r * 256 + seg * 64);
      const char* bg = (const char*)(bp + (size_t)(k0 + r) * D_ + col0 + seg * 32);
#pragma unroll
      for (int j = 0; j < 4; ++j)
        cp_async16(sb + swz256(o0 + j * 16), bg + j * 16);
    }
    CP_COMMIT();
  };

  load_step(0, 0);

  for (int c = 0; c < nsteps; ++c) {
    asm volatile("cp.async.wait_group 0;" ::: "memory");
    __syncthreads();
    // Barrier also orders step c-1's compute (other-stage readers) before
    // the writes below — no trailing barrier needed.
    if (c + 1 < nsteps) load_step(c + 1, (c + 1) & 1);

    const uint32_t sa = smA + (c & 1) * STG;
    const uint32_t sb = sa + ASTG;

#pragma unroll
    for (int kk = 0; kk < 4; ++kk) {  // 4 x k16 per 64-wide step
      uint32_t af[2][4];
#pragma unroll
      for (int mt = 0; mt < 2; ++mt) {
        const int m0 = wm * 32 + mt * 16;
        const int row = m0 + ((lid >> 3) & 1) * 8 + (lid & 7);
        const int kb = kk * 32 + ((lid >> 4) & 1) * 16;
        ldmatrix_x4(af[mt][0], af[mt][1], af[mt][2], af[mt][3],
                    sa + row * 128 + (kb ^ ((row & 7) << 4)));
      }
      uint32_t bfr[4][4];
#pragma unroll
      for (int np = 0; np < 4; ++np) {
        if constexpr (MODE != 2) {
          const int n0 = wn * 64 + np * 16;
          const int row = n0 + ((lid >> 4) & 1) * 8 + (lid & 7);
          const int kb = kk * 32 + ((lid >> 3) & 1) * 16;
          ldmatrix_x4(bfr[np][0], bfr[np][1], bfr[np][2], bfr[np][3],
                      sb + row * 128 + (kb ^ ((row & 7) << 4)));
        } else {
          // transposed load from V[tok][e]: k-rows, e-cols
          const int krow = kk * 16 + ((lid >> 3) & 1) * 8 + (lid & 7);
          const int colb = (wn * 64 + np * 16 + ((lid >> 4) & 1) * 8) * 2;
          ldmatrix_x4_trans(bfr[np][0], bfr[np][1], bfr[np][2], bfr[np][3],
                            sb + krow * 256 + (colb ^ ((krow & 7) << 4)));
        }
      }
#pragma unroll
      for (int mt = 0; mt < 2; ++mt)
#pragma unroll
        for (int nt = 0; nt < 8; ++nt)
          mma_fp16(acc[mt][nt], af[mt], bfr[nt >> 1][(nt & 1) * 2],
                   bfr[nt >> 1][(nt & 1) * 2 + 1]);
    }
  }

  // ---- epilogue: fragment (c0,c1)=(m, n..n+1), (c2,c3)=(m+8, n..n+1) ----
#pragma unroll
  for (int mt = 0; mt < 2; ++mt) {
#pragma unroll
    for (int nt = 0; nt < 8; ++nt) {
      const int m = row0 + wm * 32 + mt * 16 + (lid >> 2);
      const int n = col0 + wn * 64 + nt * 8 + 2 * (lid & 3);
      const float* cf = acc[mt][nt];
      if constexpr (MODE == 0) {
        __half* C = (bz == 0) ? g_Q16 : (bz == 1) ? g_K16 : g_V16;
#pragma unroll
        for (int hh = 0; hh < 2; ++hh) {
          const size_t o = (size_t)(m + hh * 8) * D_ + n;
          *(__half2*)(C + o) = __floats2half2_rn(cf[hh * 2], cf[hh * 2 + 1]);
        }
      } else if constexpr (MODE == 1) {
#pragma unroll
        for (int hh = 0; hh < 2; ++hh) {
          __half* sp = g_S16 + ((size_t)bz * N_ + m + hh * 8) * N_ + n;
          *(__half2*)sp =
              __floats2half2_rn(cf[hh * 2] * SCALE, cf[hh * 2 + 1] * SCALE);
        }
      } else {
#pragma unroll
        for (int hh = 0; hh < 2; ++hh) {
          float* op = out + ((size_t)bz * N_ + m + hh * 8) * D_ + n;
          op[0] = cf[hh * 2];
          op[1] = cf[hh * 2 + 1];
        }
      }
    }
  }
}

// ---------------------------------------------------------------------------
// Fused conversion: z = 0..3 -> x quarters (coalesced fp32->fp16),
//                   z = 4..6 -> transpose-convert W[d][e] -> Wt16[e][d]
// ---------------------------------------------------------------------------
__global__ __launch_bounds__(256) void conv_all_kernel(
    const float* __restrict__ x, const float* __restrict__ Wq,
    const float* __restrict__ Wk, const float* __restrict__ Wv) {
  const int z = blockIdx.z;
  if (z < 4) {
    // x quarter z: 2M elements, 1024 blocks x 256 threads x 8 elems (2 float4)
    size_t base = (size_t)z * (M_ * D_ / 4);
    size_t i = base + ((size_t)blockIdx.x * 256 + threadIdx.x) * 8;
    float4 v0 = *(const float4*)(x + i);
    float4 v1 = *(const float4*)(x + i + 4);
    __half2* o = (__half2*)(g_x16 + i);
    o[0] = __floats2half2_rn(v0.x, v0.y);
    o[1] = __floats2half2_rn(v0.z, v0.w);
    o[2] = __floats2half2_rn(v1.x, v1.y);
    o[3] = __floats2half2_rn(v1.z, v1.w);
  } else {
    const int w = z - 4;
    const float* W = (w == 0) ? Wq : (w == 1) ? Wk : Wv;
    __half* T = g_Wt16[w];
    __shared__ float t[32][33];
    // blockIdx.x in [0, 1024): 32x32 tile grid over [D_, D_]
    int e0 = (blockIdx.x & 31) * 32, d0 = (blockIdx.x >> 5) * 32;
    int tx = threadIdx.x & 31, ty = threadIdx.x >> 5;  // 32 x 8
#pragma unroll
    for (int i = 0; i < 4; ++i)
      t[ty + i * 8][tx] = W[(size_t)(d0 + ty + i * 8) * D_ + e0 + tx];
    __syncthreads();
#pragma unroll
    for (int i = 0; i < 4; ++i)
      T[(size_t)(e0 + ty + i * 8) * D_ + d0 + tx] =
          __float2half_rn(t[tx][ty + i * 8]);
  }
}

// ---------------------------------------------------------------------------
// Causal softmax: register-resident, vectorized, balanced, fp16 input.
// Block handles the row pair (q, N-1-q). Thread tid owns the contiguous
// slice [tid*8, tid*8+8): one 16B load (8 halves), exp in registers,
// 4x __half2 stores zero-padded to the 128-aligned causal tile bound.
// ---------------------------------------------------------------------------
__global__ __launch_bounds__(256) void softmax_kernel() {
  const int b = blockIdx.y;
  const int tid = threadIdx.x;

  __shared__ float redm[8], reds[8];

#pragma unroll
  for (int half = 0; half < 2; ++half) {
    const int q = half ? (N_ - 1 - blockIdx.x) : blockIdx.x;
    const __half* row = g_S16 + ((size_t)b * N_ + q) * N_;
    __half* ph = g_P16 + ((size_t)b * N_ + q) * N_;
    const int L = q + 1;
    const int wlim = ((q >> 7) + 1) << 7;  // PV reads cols [0, wlim)
    const int k0 = tid * 8;                // this thread's slice start

    // pass 1: gmem -> registers (one uint4 = 8 halves), masked, local max
    float a[8];
    if (k0 < L) {
      uint4 u = *(const uint4*)(row + k0);
      const uint32_t uu[4] = {u.x, u.y, u.z, u.w};
#pragma unroll
      for (int p = 0; p < 4; ++p) {
        float2 f = __half22float2(*(const __half2*)&uu[p]);
        a[p * 2 + 0] = (k0 + p * 2 < L) ? f.x : -1e30f;
        a[p * 2 + 1] = (k0 + p * 2 + 1 < L) ? f.y : -1e30f;
      }
    } else {
#pragma unroll
      for (int i = 0; i < 8; ++i) a[i] = -1e30f;
    }
    float m = a[0];
#pragma unroll
    for (int i = 1; i < 8; ++i) m = fmaxf(m, a[i]);
#pragma unroll
    for (int o = 16; o; o >>= 1) m = fmaxf(m, __shfl_xor_sync(~0u, m, o));
    if ((tid & 31) == 0) redm[tid >> 5] = m;
    __syncthreads();
    float m0 = redm[0];
#pragma unroll
    for (int w = 1; w < 8; ++w) m0 = fmaxf(m0, redm[w]);

    // pass 2: exp in registers, local sum (masked lanes give exp(-inf)=0)
    float sum = 0.f;
    const float c = 1.44269504f;
#pragma unroll
    for (int i = 0; i < 8; ++i) {
      a[i] = exp2f((a[i] - m0) * c);
      sum += a[i];
    }
#pragma unroll
    for (int o = 16; o; o >>= 1) sum += __shfl_xor_sync(~0u, sum, o);
    if ((tid & 31) == 0) reds[tid >> 5] = sum;
    __syncthreads();
    float s0 = 0.f;
#pragma unroll
    for (int w = 0; w < 8; ++w) s0 += reds[w];
    const float inv = 1.f / s0;

    // pass 3: normalize + 4x __half2 store (zeros land beyond L; bound wlim)
    if (k0 < wlim) {
#pragma unroll
      for (int p = 0; p < 4; ++p) {
        const int k = k0 + p * 2;
        float p0 = (k < L) ? a[p * 2] * inv : 0.f;
        float p1 = (k + 1 < L) ? a[p * 2 + 1] * inv : 0.f;
        *(__half2*)(ph + k) = __floats2half2_rn(p0, p1);
      }
    }
    __syncthreads();  // redm/reds reuse between the two rows
  }
}

// ---------------------------------------------------------------------------
extern "C" void kernel_launch(void* const* d_in, const int* in_sizes, int n_in,
                              void* d_out, int out_size) {
  const float* x  = (const float*)d_in[0];
  const float* Wq = (const float*)d_in[1];
  const float* Wk = (const float*)d_in[2];
  const float* Wv = (const float*)d_in[3];
  float* out = (float*)d_out;

  cudaFuncSetAttribute(gemm_tc<0>, cudaFuncAttributeMaxDynamicSharedMemorySize,
                       SMEM_DYN);
  cudaFuncSetAttribute(gemm_tc<1>, cudaFuncAttributeMaxDynamicSharedMemorySize,
                       SMEM_DYN);
  cudaFuncSetAttribute(gemm_tc<2>, cudaFuncAttributeMaxDynamicSharedMemorySize,
                       SMEM_DYN);

  // 1) fused conversion: x -> fp16, W -> fp16 transposed
  conv_all_kernel<<<dim3(1024, 1, 7), 256>>>(x, Wq, Wk, Wv);
  // 2) QKV projections: C[8192,1024], 128x128 tiles
  gemm_tc<0><<<dim3(D_ / 128, M_ / 128, 3), 256, SMEM_DYN>>>(nullptr);
  // 3) scores S = scale * Q K^T -> fp16 (tiles above the diagonal skipped)
  gemm_tc<1><<<dim3(N_ / 128, N_ / 128, B_), 256, SMEM_DYN>>>(nullptr);
  // 4) softmax -> P fp16 (balanced pairs, register-resident, fp16 in)
  softmax_kernel<<<dim3(N_ / 2, B_), 256>>>();
  // 5) O = P V (causally bounded K loop, heavy tiles first, V loaded direct)
  gemm_tc<2><<<dim3(D_ / 128, N_ / 128, B_), 256, SMEM_DYN>>>(out);
}